// round 14
// baseline (speedup 1.0000x reference)
#include <cuda_runtime.h>
#include <cuda_bf16.h>

// ---------------------------------------------------------------------------
// PointNetPlus (DGCNN-style) forward, fp32 baseline.
//   B=8, N=2048, K=20.
// Key simplification: EdgeConv = per-point features then neighbor-max gather.
// ---------------------------------------------------------------------------

#define B_SZ   8
#define NPTS   2048
#define KNN_K  20
#define M_TOT  (B_SZ * NPTS)          // 16384 points total

// 1/sqrt(1 + 1e-5)
#define BN_RSQ 0.9999950000374997f

// ---------------- scratch (device globals; no runtime allocation) ----------
__device__ __align__(16) float g_y[M_TOT * 1024];    // stage outputs (max 1024 ch)
__device__ __align__(16) float g_cat[M_TOT * 512];   // concat of x1..x4
__device__ int   g_idx[M_TOT * KNN_K];               // knn indices
__device__ float g_f[B_SZ * 2048];                   // pooled global features

// ---------------------------------------------------------------------------
// KNN: per block = 256 points of one batch; x cached in smem.
// neg_d = 2*inner - xx[n] - xx[m]; keep top-20 (strict >, ascending m ==
// lowest-index tie preference, matching jax top_k's chosen set).
// ---------------------------------------------------------------------------
__global__ __launch_bounds__(256) void knn_kernel(const float* __restrict__ x) {
    __shared__ float sx0[NPTS], sx1[NPTS], sx2[NPTS], sxx[NPTS];
    const int b  = blockIdx.x >> 3;
    const int n0 = (blockIdx.x & 7) * 256;
    const float* xb = x + (size_t)b * 3 * NPTS;
    for (int i = threadIdx.x; i < NPTS; i += 256) {
        float a0 = xb[i], a1 = xb[NPTS + i], a2 = xb[2 * NPTS + i];
        sx0[i] = a0; sx1[i] = a1; sx2[i] = a2;
        sxx[i] = a0 * a0 + a1 * a1 + a2 * a2;
    }
    __syncthreads();

    const int n = n0 + threadIdx.x;
    const float p0 = sx0[n], p1 = sx1[n], p2 = sx2[n], pxx = sxx[n];

    float vals[KNN_K];
    int   ids[KNN_K];
    // fill first 20
    for (int m = 0; m < KNN_K; m++) {
        float inner = p0 * sx0[m] + p1 * sx1[m] + p2 * sx2[m];
        float d = 2.0f * inner - pxx - sxx[m];
        vals[m] = d; ids[m] = m;
    }
    float vmin = vals[0]; int pmin = 0;
    #pragma unroll
    for (int j = 1; j < KNN_K; j++)
        if (vals[j] < vmin) { vmin = vals[j]; pmin = j; }

    for (int m = KNN_K; m < NPTS; m++) {
        float inner = p0 * sx0[m] + p1 * sx1[m] + p2 * sx2[m];
        float d = 2.0f * inner - pxx - sxx[m];
        if (d > vmin) {
            vals[pmin] = d; ids[pmin] = m;
            vmin = vals[0]; pmin = 0;
            #pragma unroll
            for (int j = 1; j < KNN_K; j++)
                if (vals[j] < vmin) { vmin = vals[j]; pmin = j; }
        }
    }
    int* op = g_idx + (size_t)(b * NPTS + n) * KNN_K;
    #pragma unroll
    for (int j = 0; j < KNN_K; j++) op[j] = ids[j];
}

// ---------------------------------------------------------------------------
// conv1: y[m, c] = lrelu(bn1(W1 @ x_point)), K=3, Cout=64.  y layout (M, 64).
// ---------------------------------------------------------------------------
__global__ __launch_bounds__(256) void conv1_kernel(
    const float* __restrict__ x, const float* __restrict__ W1,
    const float* __restrict__ g, const float* __restrict__ be) {
    int gid = blockIdx.x * 256 + threadIdx.x;     // m*64 + c
    int c = gid & 63, m = gid >> 6;
    int b = m >> 11, n = m & (NPTS - 1);
    const float* xb = x + (size_t)b * 3 * NPTS + n;
    float v = W1[c * 3 + 0] * xb[0] + W1[c * 3 + 1] * xb[NPTS] + W1[c * 3 + 2] * xb[2 * NPTS];
    v = v * (g[c] * BN_RSQ) + be[c];
    g_y[(size_t)m * 64 + c] = v >= 0.0f ? v : 0.2f * v;
}

// ---------------------------------------------------------------------------
// Neighbor max: out[m, c] = max_k y[(b, idx[m,k]), c].  y is (M, C) row-major,
// output goes into g_cat channel slice [coff, coff+C).
// ---------------------------------------------------------------------------
template <int C>
__global__ __launch_bounds__(128) void nmax_kernel(int coff) {
    constexpr int GS  = C / 4;        // threads per point (float4 lanes)
    constexpr int PPB = 128 / GS;     // points per block
    const int p    = blockIdx.x * PPB + threadIdx.x / GS;
    const int lane = threadIdx.x % GS;
    const int b    = p >> 11;
    const int base = b * NPTS;
    const int c4   = lane * 4;
    const int* ip  = g_idx + (size_t)p * KNN_K;

    int j0 = ip[0];
    float4 acc = *(const float4*)&g_y[(size_t)(base + j0) * C + c4];
    #pragma unroll 4
    for (int k = 1; k < KNN_K; k++) {
        int j = ip[k];
        float4 v = *(const float4*)&g_y[(size_t)(base + j) * C + c4];
        acc.x = fmaxf(acc.x, v.x); acc.y = fmaxf(acc.y, v.y);
        acc.z = fmaxf(acc.z, v.z); acc.w = fmaxf(acc.w, v.w);
    }
    *(float4*)&g_cat[(size_t)p * 512 + coff + c4] = acc;
}

// ---------------------------------------------------------------------------
// Fused SGEMM + BN + LReLU.
//   A = g_cat + a_off (M x K, lda = 512), W = (Nout x K) row-major,
//   out = g_y (M x Nout, ldc = Nout).
// Tiles: 64x64x16, 256 threads, 4x4 per thread, float4 smem reads.
// grid = (M/64, Nout/64)
// ---------------------------------------------------------------------------
__global__ __launch_bounds__(256) void gemm_bn_lrelu_kernel(
    int a_off, const float* __restrict__ W,
    const float* __restrict__ gamma, const float* __restrict__ beta,
    int ldc, int K) {
    __shared__ float As[16][64];
    __shared__ float Bs[16][64];

    const int tid  = threadIdx.x;
    const int row0 = blockIdx.x * 64;
    const int col0 = blockIdx.y * 64;
    const int tx = tid & 15, ty = tid >> 4;
    const int lm = tid >> 2;            // 0..63
    const int lk = (tid & 3) << 2;      // 0,4,8,12

    const float* Ap = g_cat + (size_t)(row0 + lm) * 512 + a_off + lk;
    const float* Wp = W + (size_t)(col0 + lm) * K + lk;

    float acc[4][4] = {};

    for (int k0 = 0; k0 < K; k0 += 16) {
        float4 av = *(const float4*)(Ap + k0);
        float4 bv = *(const float4*)(Wp + k0);
        As[lk + 0][lm] = av.x; As[lk + 1][lm] = av.y;
        As[lk + 2][lm] = av.z; As[lk + 3][lm] = av.w;
        Bs[lk + 0][lm] = bv.x; Bs[lk + 1][lm] = bv.y;
        Bs[lk + 2][lm] = bv.z; Bs[lk + 3][lm] = bv.w;
        __syncthreads();
        #pragma unroll
        for (int kk = 0; kk < 16; kk++) {
            float4 a = *(const float4*)&As[kk][ty << 2];
            float4 b = *(const float4*)&Bs[kk][tx << 2];
            acc[0][0] = fmaf(a.x, b.x, acc[0][0]);
            acc[0][1] = fmaf(a.x, b.y, acc[0][1]);
            acc[0][2] = fmaf(a.x, b.z, acc[0][2]);
            acc[0][3] = fmaf(a.x, b.w, acc[0][3]);
            acc[1][0] = fmaf(a.y, b.x, acc[1][0]);
            acc[1][1] = fmaf(a.y, b.y, acc[1][1]);
            acc[1][2] = fmaf(a.y, b.z, acc[1][2]);
            acc[1][3] = fmaf(a.y, b.w, acc[1][3]);
            acc[2][0] = fmaf(a.z, b.x, acc[2][0]);
            acc[2][1] = fmaf(a.z, b.y, acc[2][1]);
            acc[2][2] = fmaf(a.z, b.z, acc[2][2]);
            acc[2][3] = fmaf(a.z, b.w, acc[2][3]);
            acc[3][0] = fmaf(a.w, b.x, acc[3][0]);
            acc[3][1] = fmaf(a.w, b.y, acc[3][1]);
            acc[3][2] = fmaf(a.w, b.z, acc[3][2]);
            acc[3][3] = fmaf(a.w, b.w, acc[3][3]);
        }
        __syncthreads();
    }

    const int cb = col0 + (tx << 2);
    float4 gv = *(const float4*)&gamma[cb];
    float4 bb = *(const float4*)&beta[cb];
    float s0 = gv.x * BN_RSQ, s1 = gv.y * BN_RSQ, s2 = gv.z * BN_RSQ, s3 = gv.w * BN_RSQ;
    #pragma unroll
    for (int i = 0; i < 4; i++) {
        int r = row0 + (ty << 2) + i;
        float4 o;
        o.x = acc[i][0] * s0 + bb.x;
        o.y = acc[i][1] * s1 + bb.y;
        o.z = acc[i][2] * s2 + bb.z;
        o.w = acc[i][3] * s3 + bb.w;
        o.x = o.x >= 0.0f ? o.x : 0.2f * o.x;
        o.y = o.y >= 0.0f ? o.y : 0.2f * o.y;
        o.z = o.z >= 0.0f ? o.z : 0.2f * o.z;
        o.w = o.w >= 0.0f ? o.w : 0.2f * o.w;
        *(float4*)&g_y[(size_t)r * ldc + cb] = o;
    }
}

// ---------------------------------------------------------------------------
// Global max+mean pooling over N: h = g_y (B, N, 1024) -> g_f (B, 2048)
// grid (B, 8), 128 threads: one channel per thread.
// ---------------------------------------------------------------------------
__global__ __launch_bounds__(128) void reduce_kernel() {
    const int b = blockIdx.x;
    const int c = blockIdx.y * 128 + threadIdx.x;
    const float* hp = g_y + (size_t)b * NPTS * 1024 + c;
    float mx = -1e30f, sm = 0.0f;
    for (int n = 0; n < NPTS; n++) {
        float v = hp[(size_t)n * 1024];
        mx = fmaxf(mx, v);
        sm += v;
    }
    g_f[b * 2048 + c]        = mx;
    g_f[b * 2048 + 1024 + c] = sm * (1.0f / 2048.0f);
}

// ---------------------------------------------------------------------------
// FC head: f(2048) -> 512 -> 256 -> 40, fused. One block per batch row,
// warp-per-output-row dot products (coalesced weight reads).
// ---------------------------------------------------------------------------
__global__ __launch_bounds__(512) void head_kernel(
    const float* __restrict__ L1W, const float* __restrict__ g6, const float* __restrict__ b6,
    const float* __restrict__ L2W, const float* __restrict__ L2b,
    const float* __restrict__ g7, const float* __restrict__ b7,
    const float* __restrict__ L3W, const float* __restrict__ L3b,
    float* __restrict__ out) {
    __shared__ float fin[2048];
    __shared__ float f1[512];
    __shared__ float f2[256];
    const int b = blockIdx.x, tid = threadIdx.x;
    const int wid = tid >> 5, lane = tid & 31;

    for (int i = tid; i < 2048; i += 512) fin[i] = g_f[b * 2048 + i];
    __syncthreads();

    for (int row = wid; row < 512; row += 16) {
        const float* wp = L1W + (size_t)row * 2048;
        float acc = 0.0f;
        for (int k = lane; k < 2048; k += 32) acc = fmaf(fin[k], wp[k], acc);
        #pragma unroll
        for (int o = 16; o; o >>= 1) acc += __shfl_xor_sync(0xFFFFFFFFu, acc, o);
        if (lane == 0) {
            float v = acc * (g6[row] * BN_RSQ) + b6[row];
            f1[row] = v >= 0.0f ? v : 0.2f * v;
        }
    }
    __syncthreads();

    for (int row = wid; row < 256; row += 16) {
        const float* wp = L2W + (size_t)row * 512;
        float acc = 0.0f;
        for (int k = lane; k < 512; k += 32) acc = fmaf(f1[k], wp[k], acc);
        #pragma unroll
        for (int o = 16; o; o >>= 1) acc += __shfl_xor_sync(0xFFFFFFFFu, acc, o);
        if (lane == 0) {
            float v = (acc + L2b[row]) * (g7[row] * BN_RSQ) + b7[row];
            f2[row] = v >= 0.0f ? v : 0.2f * v;
        }
    }
    __syncthreads();

    for (int row = wid; row < 40; row += 16) {
        const float* wp = L3W + (size_t)row * 256;
        float acc = 0.0f;
        for (int k = lane; k < 256; k += 32) acc = fmaf(f2[k], wp[k], acc);
        #pragma unroll
        for (int o = 16; o; o >>= 1) acc += __shfl_xor_sync(0xFFFFFFFFu, acc, o);
        if (lane == 0) out[b * 40 + row] = acc + L3b[row];
    }
}

// ---------------------------------------------------------------------------
extern "C" void kernel_launch(void* const* d_in, const int* in_sizes, int n_in,
                              void* d_out, int out_size) {
    (void)in_sizes; (void)n_in; (void)out_size;
    const float* x   = (const float*)d_in[0];
    const float* W1  = (const float*)d_in[1];
    const float* W2  = (const float*)d_in[2];
    const float* W3  = (const float*)d_in[3];
    const float* W4  = (const float*)d_in[4];
    const float* W5  = (const float*)d_in[5];
    const float* g1  = (const float*)d_in[6];
    const float* b1  = (const float*)d_in[7];
    const float* g2  = (const float*)d_in[8];
    const float* b2  = (const float*)d_in[9];
    const float* g3  = (const float*)d_in[10];
    const float* b3  = (const float*)d_in[11];
    const float* g4  = (const float*)d_in[12];
    const float* b4  = (const float*)d_in[13];
    const float* g5  = (const float*)d_in[14];
    const float* b5  = (const float*)d_in[15];
    const float* g6  = (const float*)d_in[16];
    const float* b6  = (const float*)d_in[17];
    const float* g7  = (const float*)d_in[18];
    const float* b7  = (const float*)d_in[19];
    const float* L1W = (const float*)d_in[20];
    const float* L2W = (const float*)d_in[21];
    const float* L2b = (const float*)d_in[22];
    const float* L3W = (const float*)d_in[23];
    const float* L3b = (const float*)d_in[24];
    float* out = (float*)d_out;

    // 1) KNN indices
    knn_kernel<<<B_SZ * 8, 256>>>(x);

    // 2) conv1 (K=3) -> y (M,64); nmax -> cat[:, 0:64]
    conv1_kernel<<<(M_TOT * 64) / 256, 256>>>(x, W1, g1, b1);
    nmax_kernel<64><<<M_TOT / 8, 128>>>(0);

    // 3) conv2: (M,64) @ W2^T -> y (M,64); nmax -> cat[:, 64:128]
    gemm_bn_lrelu_kernel<<<dim3(M_TOT / 64, 1), 256>>>(0, W2, g2, b2, 64, 64);
    nmax_kernel<64><<<M_TOT / 8, 128>>>(64);

    // 4) conv3: (M,64) @ W3^T -> y (M,128); nmax -> cat[:, 128:256]
    gemm_bn_lrelu_kernel<<<dim3(M_TOT / 64, 2), 256>>>(64, W3, g3, b3, 128, 64);
    nmax_kernel<128><<<M_TOT / 4, 128>>>(128);

    // 5) conv4: (M,128) @ W4^T -> y (M,256); nmax -> cat[:, 256:512]
    gemm_bn_lrelu_kernel<<<dim3(M_TOT / 64, 4), 256>>>(128, W4, g4, b4, 256, 128);
    nmax_kernel<256><<<M_TOT / 2, 128>>>(256);

    // 6) conv5: (M,512) @ W5^T -> h = y (M,1024)
    gemm_bn_lrelu_kernel<<<dim3(M_TOT / 64, 16), 256>>>(0, W5, g5, b5, 1024, 512);

    // 7) max+mean pool -> g_f (B, 2048)
    reduce_kernel<<<dim3(B_SZ, 8), 128>>>();

    // 8) FC head -> out (B, 40)
    head_kernel<<<B_SZ, 512>>>(L1W, g6, b6, L2W, L2b, g7, b7, L3W, L3b, out);
}

// round 16
// speedup vs baseline: 1.3575x; 1.3575x over previous
#include <cuda_runtime.h>
#include <cuda_bf16.h>
#include <cstdint>

// ---------------------------------------------------------------------------
// PointNetPlus (DGCNN-style) forward. B=8, N=2048, K=20.
// EdgeConv = per-point GEMM then neighbor-max gather.
// conv4/conv5 on mma.sync bf16x3 (split precision) tensor cores (sm_80+ path;
// tcgen05 unavailable: harness compiles for base sm_103 target).
// ---------------------------------------------------------------------------

#define B_SZ   8
#define NPTS   2048
#define KNN_K  20
#define M_TOT  (B_SZ * NPTS)          // 16384 points total

// 1/sqrt(1 + 1e-5)
#define BN_RSQ 0.9999950000374997f

// ---------------- scratch (device globals; no runtime allocation) ----------
__device__ __align__(16) float g_y[M_TOT * 1024];           // stage outputs
__device__ __align__(16) float g_cat[M_TOT * 512];          // concat x1..x4 fp32
__device__ __align__(16) __nv_bfloat16 g_cath[M_TOT * 512]; // bf16 hi of cat
__device__ __align__(16) __nv_bfloat16 g_catl[M_TOT * 512]; // bf16 lo of cat
__device__ __align__(16) __nv_bfloat16 g_w4h[256 * 128];
__device__ __align__(16) __nv_bfloat16 g_w4l[256 * 128];
__device__ __align__(16) __nv_bfloat16 g_w5h[1024 * 512];
__device__ __align__(16) __nv_bfloat16 g_w5l[1024 * 512];
__device__ int   g_idx[M_TOT * KNN_K];
__device__ float g_f[B_SZ * 2048];

// ======================= PTX helpers ========================================
__device__ __forceinline__ uint32_t smem_u32(const void* p) {
    uint32_t a;
    asm("{ .reg .u64 t; cvta.to.shared.u64 t, %1; cvt.u32.u64 %0, t; }"
        : "=r"(a) : "l"(p));
    return a;
}

#define CP16(dst, src)                                                         \
    asm volatile("cp.async.cg.shared.global [%0], [%1], 16;"                   \
                 :: "r"(dst), "l"(src))

#define LDSM4(r, addr)                                                         \
    asm volatile("ldmatrix.sync.aligned.m8n8.x4.shared.b16 {%0,%1,%2,%3}, [%4];" \
                 : "=r"((r)[0]), "=r"((r)[1]), "=r"((r)[2]), "=r"((r)[3])       \
                 : "r"(addr))

#define MMA16816(d, a, b0, b1)                                                 \
    asm volatile("mma.sync.aligned.m16n8k16.row.col.f32.bf16.bf16.f32 "        \
                 "{%0,%1,%2,%3}, {%4,%5,%6,%7}, {%8,%9}, {%0,%1,%2,%3};"       \
                 : "+f"((d)[0]), "+f"((d)[1]), "+f"((d)[2]), "+f"((d)[3])      \
                 : "r"((a)[0]), "r"((a)[1]), "r"((a)[2]), "r"((a)[3]),         \
                   "r"(b0), "r"(b1))

__device__ __forceinline__ uint2 pack_bf16x4(float a, float b, float c, float d) {
    __nv_bfloat162 p0 = __floats2bfloat162_rn(a, b);
    __nv_bfloat162 p1 = __floats2bfloat162_rn(c, d);
    uint2 r;
    r.x = *(uint32_t*)&p0;
    r.y = *(uint32_t*)&p1;
    return r;
}

// ---------------------------------------------------------------------------
// KNN
// ---------------------------------------------------------------------------
__global__ __launch_bounds__(256) void knn_kernel(const float* __restrict__ x) {
    __shared__ float sx0[NPTS], sx1[NPTS], sx2[NPTS], sxx[NPTS];
    const int b  = blockIdx.x >> 3;
    const int n0 = (blockIdx.x & 7) * 256;
    const float* xb = x + (size_t)b * 3 * NPTS;
    for (int i = threadIdx.x; i < NPTS; i += 256) {
        float a0 = xb[i], a1 = xb[NPTS + i], a2 = xb[2 * NPTS + i];
        sx0[i] = a0; sx1[i] = a1; sx2[i] = a2;
        sxx[i] = a0 * a0 + a1 * a1 + a2 * a2;
    }
    __syncthreads();

    const int n = n0 + threadIdx.x;
    const float p0 = sx0[n], p1 = sx1[n], p2 = sx2[n], pxx = sxx[n];

    float vals[KNN_K];
    int   ids[KNN_K];
    for (int m = 0; m < KNN_K; m++) {
        float inner = p0 * sx0[m] + p1 * sx1[m] + p2 * sx2[m];
        float d = 2.0f * inner - pxx - sxx[m];
        vals[m] = d; ids[m] = m;
    }
    float vmin = vals[0]; int pmin = 0;
    #pragma unroll
    for (int j = 1; j < KNN_K; j++)
        if (vals[j] < vmin) { vmin = vals[j]; pmin = j; }

    for (int m = KNN_K; m < NPTS; m++) {
        float inner = p0 * sx0[m] + p1 * sx1[m] + p2 * sx2[m];
        float d = 2.0f * inner - pxx - sxx[m];
        if (d > vmin) {
            vals[pmin] = d; ids[pmin] = m;
            vmin = vals[0]; pmin = 0;
            #pragma unroll
            for (int j = 1; j < KNN_K; j++)
                if (vals[j] < vmin) { vmin = vals[j]; pmin = j; }
        }
    }
    int* op = g_idx + (size_t)(b * NPTS + n) * KNN_K;
    #pragma unroll
    for (int j = 0; j < KNN_K; j++) op[j] = ids[j];
}

// ---------------------------------------------------------------------------
// conv1 (K=3, Cout=64)
// ---------------------------------------------------------------------------
__global__ __launch_bounds__(256) void conv1_kernel(
    const float* __restrict__ x, const float* __restrict__ W1,
    const float* __restrict__ g, const float* __restrict__ be) {
    int gid = blockIdx.x * 256 + threadIdx.x;
    int c = gid & 63, m = gid >> 6;
    int b = m >> 11, n = m & (NPTS - 1);
    const float* xb = x + (size_t)b * 3 * NPTS + n;
    float v = W1[c * 3 + 0] * xb[0] + W1[c * 3 + 1] * xb[NPTS] + W1[c * 3 + 2] * xb[2 * NPTS];
    v = v * (g[c] * BN_RSQ) + be[c];
    g_y[(size_t)m * 64 + c] = v >= 0.0f ? v : 0.2f * v;
}

// ---------------------------------------------------------------------------
// Neighbor max gather; writes fp32 g_cat slice AND bf16 hi/lo splits.
// ---------------------------------------------------------------------------
template <int C>
__global__ __launch_bounds__(128) void nmax_kernel(int coff) {
    constexpr int GS  = C / 4;
    constexpr int PPB = 128 / GS;
    const int p    = blockIdx.x * PPB + threadIdx.x / GS;
    const int lane = threadIdx.x % GS;
    const int b    = p >> 11;
    const int base = b * NPTS;
    const int c4   = lane * 4;
    const int* ip  = g_idx + (size_t)p * KNN_K;

    int j0 = ip[0];
    float4 acc = *(const float4*)&g_y[(size_t)(base + j0) * C + c4];
    #pragma unroll 4
    for (int k = 1; k < KNN_K; k++) {
        int j = ip[k];
        float4 v = *(const float4*)&g_y[(size_t)(base + j) * C + c4];
        acc.x = fmaxf(acc.x, v.x); acc.y = fmaxf(acc.y, v.y);
        acc.z = fmaxf(acc.z, v.z); acc.w = fmaxf(acc.w, v.w);
    }
    const size_t off = (size_t)p * 512 + coff + c4;
    *(float4*)&g_cat[off] = acc;

    __nv_bfloat16 hx = __float2bfloat16(acc.x);
    __nv_bfloat16 hy = __float2bfloat16(acc.y);
    __nv_bfloat16 hz = __float2bfloat16(acc.z);
    __nv_bfloat16 hw = __float2bfloat16(acc.w);
    float lx = acc.x - __bfloat162float(hx);
    float ly = acc.y - __bfloat162float(hy);
    float lz = acc.z - __bfloat162float(hz);
    float lw = acc.w - __bfloat162float(hw);
    *(uint2*)&g_cath[off] = pack_bf16x4(acc.x, acc.y, acc.z, acc.w);
    *(uint2*)&g_catl[off] = pack_bf16x4(lx, ly, lz, lw);
}

// ---------------------------------------------------------------------------
// Weight split: fp32 -> bf16 hi/lo.  wsel: 0 -> W4 buffers, 1 -> W5 buffers.
// ---------------------------------------------------------------------------
__global__ __launch_bounds__(256) void wsplit_kernel(const float* __restrict__ src,
                                                     int n, int wsel) {
    int i = blockIdx.x * 256 + threadIdx.x;
    if (i >= n) return;
    __nv_bfloat16* dh = wsel ? g_w5h : g_w4h;
    __nv_bfloat16* dl = wsel ? g_w5l : g_w4l;
    float v = src[i];
    __nv_bfloat16 h = __float2bfloat16(v);
    dh[i] = h;
    dl[i] = __float2bfloat16(v - __bfloat162float(h));
}

// ---------------------------------------------------------------------------
// bf16x3 split-precision GEMM + BN + LReLU on mma.sync.m16n8k16.
//   A = g_cath/g_catl (M x 512 row-major, cols [a_off, a_off+K))
//   B = W hi/lo (Nout x K row-major)  -> B operand is "col" (K contiguous / n)
//   out = g_y (M x ldc fp32)
// CTA tile 128x128, K chunk 32, cp.async double buffer.
// 8 warps: warp_m = wid&3 (32 rows each), warp_n = wid>>2 (64 cols each).
// grid = (M/128, Nout/128), block = 256.
// smem rows padded to 80B (40 bf16) -> conflict-free ldmatrix.
// ---------------------------------------------------------------------------
#define MM_AH    0
#define MM_AL    10240
#define MM_BH    20480
#define MM_BL    30720
#define MM_STAGE 40960
#define MM_GB    (2 * MM_STAGE)            // gamma(512B) + beta(512B)
#define MM_SMEM  (MM_GB + 1024)

__device__ __forceinline__ void mm_issue_chunk(
    uint32_t sbase,
    const __nv_bfloat16* __restrict__ Ah, const __nv_bfloat16* __restrict__ Al,
    const __nv_bfloat16* __restrict__ Bh, const __nv_bfloat16* __restrict__ Bl,
    int ko, int K, int tid) {
    #pragma unroll
    for (int seg = tid; seg < 512; seg += 256) {
        int r = seg >> 2, q = seg & 3;
        uint32_t so = (uint32_t)(r * 80 + q * 16);
        size_t aoff = (size_t)r * 512 + ko + q * 8;
        size_t boff = (size_t)r * K + ko + q * 8;
        CP16(sbase + MM_AH + so, Ah + aoff);
        CP16(sbase + MM_AL + so, Al + aoff);
        CP16(sbase + MM_BH + so, Bh + boff);
        CP16(sbase + MM_BL + so, Bl + boff);
    }
}

__global__ __launch_bounds__(256) void mma_gemm_kernel(
    int a_off, int wsel,
    const float* __restrict__ gamma, const float* __restrict__ beta,
    int ldc, int K) {
    extern __shared__ char smem[];
    const uint32_t sb = smem_u32(smem);
    const int tid = threadIdx.x, lane = tid & 31, wid = tid >> 5;
    const int warp_m = wid & 3, warp_n = wid >> 2;
    const int row0 = blockIdx.x * 128, col0 = blockIdx.y * 128;

    const __nv_bfloat16* Ah = g_cath + (size_t)row0 * 512 + a_off;
    const __nv_bfloat16* Al = g_catl + (size_t)row0 * 512 + a_off;
    const __nv_bfloat16* Bh = (wsel ? g_w5h : g_w4h) + (size_t)col0 * K;
    const __nv_bfloat16* Bl = (wsel ? g_w5l : g_w4l) + (size_t)col0 * K;

    if (tid < 128) {
        ((float*)(smem + MM_GB))[tid]       = gamma[col0 + tid] * BN_RSQ;
        ((float*)(smem + MM_GB + 512))[tid] = beta[col0 + tid];
    }

    // lane-derived ldmatrix row/byte selectors
    const int arow  = (lane & 7) + ((lane >> 3) & 1) * 8;   // A: m within 16
    const int abyte = (lane >> 4) * 16;                     // A: k-half
    const int brow  = (lane & 7) + (lane >> 4) * 8;         // B: n within 16
    const int bbyte = ((lane >> 3) & 1) * 16;               // B: k-half

    float acc[2][8][4] = {};

    const int nchunk = K >> 5;
    mm_issue_chunk(sb, Ah, Al, Bh, Bl, 0, K, tid);
    asm volatile("cp.async.commit_group;" ::: "memory");

    for (int c = 0; c < nchunk; c++) {
        if (c + 1 < nchunk) {
            mm_issue_chunk(sb + ((c + 1) & 1) * MM_STAGE, Ah, Al, Bh, Bl,
                           (c + 1) << 5, K, tid);
            asm volatile("cp.async.commit_group;" ::: "memory");
            asm volatile("cp.async.wait_group 1;" ::: "memory");
        } else {
            asm volatile("cp.async.wait_group 0;" ::: "memory");
        }
        __syncthreads();

        const uint32_t st = sb + (c & 1) * MM_STAGE;
        #pragma unroll
        for (int ks = 0; ks < 2; ks++) {
            const int kb = ks * 32;                         // 16 elems * 2B
            uint32_t ah[2][4], al[2][4];
            #pragma unroll
            for (int mt = 0; mt < 2; mt++) {
                uint32_t aaddr = st + MM_AH +
                    (uint32_t)((warp_m * 32 + mt * 16 + arow) * 80 + abyte + kb);
                LDSM4(ah[mt], aaddr);
                LDSM4(al[mt], aaddr + (MM_AL - MM_AH));
            }
            #pragma unroll
            for (int nt = 0; nt < 4; nt++) {
                uint32_t bh[4], bl[4];
                uint32_t baddr = st + MM_BH +
                    (uint32_t)((warp_n * 64 + nt * 16 + brow) * 80 + bbyte + kb);
                LDSM4(bh, baddr);
                LDSM4(bl, baddr + (MM_BL - MM_BH));
                #pragma unroll
                for (int mt = 0; mt < 2; mt++) {
                    MMA16816(acc[mt][nt * 2 + 0], ah[mt], bh[0], bh[1]);
                    MMA16816(acc[mt][nt * 2 + 0], ah[mt], bl[0], bl[1]);
                    MMA16816(acc[mt][nt * 2 + 0], al[mt], bh[0], bh[1]);
                    MMA16816(acc[mt][nt * 2 + 1], ah[mt], bh[2], bh[3]);
                    MMA16816(acc[mt][nt * 2 + 1], ah[mt], bl[2], bl[3]);
                    MMA16816(acc[mt][nt * 2 + 1], al[mt], bh[2], bh[3]);
                }
            }
        }
        __syncthreads();
    }

    // Epilogue: BN + LReLU, float2 stores.
    const float* sg = (const float*)(smem + MM_GB);
    const float* sbta = (const float*)(smem + MM_GB + 512);
    #pragma unroll
    for (int mt = 0; mt < 2; mt++) {
        const int r0g = row0 + warp_m * 32 + mt * 16 + (lane >> 2);
        #pragma unroll
        for (int n8 = 0; n8 < 8; n8++) {
            const int cl = warp_n * 64 + n8 * 8 + (lane & 3) * 2;
            float s0 = sg[cl], s1 = sg[cl + 1];
            float t0 = sbta[cl], t1 = sbta[cl + 1];
            float v;
            float2 o;
            v = acc[mt][n8][0] * s0 + t0; o.x = v >= 0.0f ? v : 0.2f * v;
            v = acc[mt][n8][1] * s1 + t1; o.y = v >= 0.0f ? v : 0.2f * v;
            *(float2*)&g_y[(size_t)r0g * ldc + col0 + cl] = o;
            v = acc[mt][n8][2] * s0 + t0; o.x = v >= 0.0f ? v : 0.2f * v;
            v = acc[mt][n8][3] * s1 + t1; o.y = v >= 0.0f ? v : 0.2f * v;
            *(float2*)&g_y[(size_t)(r0g + 8) * ldc + col0 + cl] = o;
        }
    }
}

// ---------------------------------------------------------------------------
// fp32 SGEMM + BN + LReLU (small conv2/conv3).
// ---------------------------------------------------------------------------
__global__ __launch_bounds__(256) void gemm_bn_lrelu_kernel(
    int a_off, const float* __restrict__ W,
    const float* __restrict__ gamma, const float* __restrict__ beta,
    int ldc, int K) {
    __shared__ float As[16][64];
    __shared__ float Bs[16][64];

    const int tid  = threadIdx.x;
    const int row0 = blockIdx.x * 64;
    const int col0 = blockIdx.y * 64;
    const int tx = tid & 15, ty = tid >> 4;
    const int lm = tid >> 2;
    const int lk = (tid & 3) << 2;

    const float* Ap = g_cat + (size_t)(row0 + lm) * 512 + a_off + lk;
    const float* Wp = W + (size_t)(col0 + lm) * K + lk;

    float acc[4][4] = {};

    for (int k0 = 0; k0 < K; k0 += 16) {
        float4 av = *(const float4*)(Ap + k0);
        float4 bv = *(const float4*)(Wp + k0);
        As[lk + 0][lm] = av.x; As[lk + 1][lm] = av.y;
        As[lk + 2][lm] = av.z; As[lk + 3][lm] = av.w;
        Bs[lk + 0][lm] = bv.x; Bs[lk + 1][lm] = bv.y;
        Bs[lk + 2][lm] = bv.z; Bs[lk + 3][lm] = bv.w;
        __syncthreads();
        #pragma unroll
        for (int kk = 0; kk < 16; kk++) {
            float4 a = *(const float4*)&As[kk][ty << 2];
            float4 b = *(const float4*)&Bs[kk][tx << 2];
            acc[0][0] = fmaf(a.x, b.x, acc[0][0]);
            acc[0][1] = fmaf(a.x, b.y, acc[0][1]);
            acc[0][2] = fmaf(a.x, b.z, acc[0][2]);
            acc[0][3] = fmaf(a.x, b.w, acc[0][3]);
            acc[1][0] = fmaf(a.y, b.x, acc[1][0]);
            acc[1][1] = fmaf(a.y, b.y, acc[1][1]);
            acc[1][2] = fmaf(a.y, b.z, acc[1][2]);
            acc[1][3] = fmaf(a.y, b.w, acc[1][3]);
            acc[2][0] = fmaf(a.z, b.x, acc[2][0]);
            acc[2][1] = fmaf(a.z, b.y, acc[2][1]);
            acc[2][2] = fmaf(a.z, b.z, acc[2][2]);
            acc[2][3] = fmaf(a.z, b.w, acc[2][3]);
            acc[3][0] = fmaf(a.w, b.x, acc[3][0]);
            acc[3][1] = fmaf(a.w, b.y, acc[3][1]);
            acc[3][2] = fmaf(a.w, b.z, acc[3][2]);
            acc[3][3] = fmaf(a.w, b.w, acc[3][3]);
        }
        __syncthreads();
    }

    const int cb = col0 + (tx << 2);
    float4 gv = *(const float4*)&gamma[cb];
    float4 bb = *(const float4*)&beta[cb];
    float s0 = gv.x * BN_RSQ, s1 = gv.y * BN_RSQ, s2 = gv.z * BN_RSQ, s3 = gv.w * BN_RSQ;
    #pragma unroll
    for (int i = 0; i < 4; i++) {
        int r = row0 + (ty << 2) + i;
        float4 o;
        o.x = acc[i][0] * s0 + bb.x;
        o.y = acc[i][1] * s1 + bb.y;
        o.z = acc[i][2] * s2 + bb.z;
        o.w = acc[i][3] * s3 + bb.w;
        o.x = o.x >= 0.0f ? o.x : 0.2f * o.x;
        o.y = o.y >= 0.0f ? o.y : 0.2f * o.y;
        o.z = o.z >= 0.0f ? o.z : 0.2f * o.z;
        o.w = o.w >= 0.0f ? o.w : 0.2f * o.w;
        *(float4*)&g_y[(size_t)r * ldc + cb] = o;
    }
}

// ---------------------------------------------------------------------------
// Global max+mean pooling over N: g_y (B, N, 1024) -> g_f (B, 2048)
// ---------------------------------------------------------------------------
__global__ __launch_bounds__(128) void reduce_kernel() {
    const int b = blockIdx.x;
    const int c = blockIdx.y * 128 + threadIdx.x;
    const float* hp = g_y + (size_t)b * NPTS * 1024 + c;
    float mx0 = -1e30f, mx1 = -1e30f, mx2 = -1e30f, mx3 = -1e30f;
    float s0 = 0.0f, s1 = 0.0f, s2 = 0.0f, s3 = 0.0f;
    for (int n = 0; n < NPTS; n += 4) {
        float v0 = hp[(size_t)(n + 0) * 1024];
        float v1 = hp[(size_t)(n + 1) * 1024];
        float v2 = hp[(size_t)(n + 2) * 1024];
        float v3 = hp[(size_t)(n + 3) * 1024];
        mx0 = fmaxf(mx0, v0); s0 += v0;
        mx1 = fmaxf(mx1, v1); s1 += v1;
        mx2 = fmaxf(mx2, v2); s2 += v2;
        mx3 = fmaxf(mx3, v3); s3 += v3;
    }
    g_f[b * 2048 + c]        = fmaxf(fmaxf(mx0, mx1), fmaxf(mx2, mx3));
    g_f[b * 2048 + 1024 + c] = (s0 + s1 + s2 + s3) * (1.0f / 2048.0f);
}

// ---------------------------------------------------------------------------
// FC head
// ---------------------------------------------------------------------------
__global__ __launch_bounds__(512) void head_kernel(
    const float* __restrict__ L1W, const float* __restrict__ g6, const float* __restrict__ b6,
    const float* __restrict__ L2W, const float* __restrict__ L2b,
    const float* __restrict__ g7, const float* __restrict__ b7,
    const float* __restrict__ L3W, const float* __restrict__ L3b,
    float* __restrict__ out) {
    __shared__ float fin[2048];
    __shared__ float f1[512];
    __shared__ float f2[256];
    const int b = blockIdx.x, tid = threadIdx.x;
    const int wid = tid >> 5, lane = tid & 31;

    for (int i = tid; i < 2048; i += 512) fin[i] = g_f[b * 2048 + i];
    __syncthreads();

    for (int row = wid; row < 512; row += 16) {
        const float* wp = L1W + (size_t)row * 2048;
        float acc = 0.0f;
        for (int k = lane; k < 2048; k += 32) acc = fmaf(fin[k], wp[k], acc);
        #pragma unroll
        for (int o = 16; o; o >>= 1) acc += __shfl_xor_sync(0xFFFFFFFFu, acc, o);
        if (lane == 0) {
            float v = acc * (g6[row] * BN_RSQ) + b6[row];
            f1[row] = v >= 0.0f ? v : 0.2f * v;
        }
    }
    __syncthreads();

    for (int row = wid; row < 256; row += 16) {
        const float* wp = L2W + (size_t)row * 512;
        float acc = 0.0f;
        for (int k = lane; k < 512; k += 32) acc = fmaf(f1[k], wp[k], acc);
        #pragma unroll
        for (int o = 16; o; o >>= 1) acc += __shfl_xor_sync(0xFFFFFFFFu, acc, o);
        if (lane == 0) {
            float v = (acc + L2b[row]) * (g7[row] * BN_RSQ) + b7[row];
            f2[row] = v >= 0.0f ? v : 0.2f * v;
        }
    }
    __syncthreads();

    for (int row = wid; row < 40; row += 16) {
        const float* wp = L3W + (size_t)row * 256;
        float acc = 0.0f;
        for (int k = lane; k < 256; k += 32) acc = fmaf(f2[k], wp[k], acc);
        #pragma unroll
        for (int o = 16; o; o >>= 1) acc += __shfl_xor_sync(0xFFFFFFFFu, acc, o);
        if (lane == 0) out[b * 40 + row] = acc + L3b[row];
    }
}

// ---------------------------------------------------------------------------
extern "C" void kernel_launch(void* const* d_in, const int* in_sizes, int n_in,
                              void* d_out, int out_size) {
    (void)in_sizes; (void)n_in; (void)out_size;
    const float* x   = (const float*)d_in[0];
    const float* W1  = (const float*)d_in[1];
    const float* W2  = (const float*)d_in[2];
    const float* W3  = (const float*)d_in[3];
    const float* W4  = (const float*)d_in[4];
    const float* W5  = (const float*)d_in[5];
    const float* g1  = (const float*)d_in[6];
    const float* b1  = (const float*)d_in[7];
    const float* g2  = (const float*)d_in[8];
    const float* b2  = (const float*)d_in[9];
    const float* g3  = (const float*)d_in[10];
    const float* b3  = (const float*)d_in[11];
    const float* g4  = (const float*)d_in[12];
    const float* b4  = (const float*)d_in[13];
    const float* g5  = (const float*)d_in[14];
    const float* b5  = (const float*)d_in[15];
    const float* g6  = (const float*)d_in[16];
    const float* b6  = (const float*)d_in[17];
    const float* g7  = (const float*)d_in[18];
    const float* b7  = (const float*)d_in[19];
    const float* L1W = (const float*)d_in[20];
    const float* L2W = (const float*)d_in[21];
    const float* L2b = (const float*)d_in[22];
    const float* L3W = (const float*)d_in[23];
    const float* L3b = (const float*)d_in[24];
    float* out = (float*)d_out;

    cudaFuncSetAttribute(mma_gemm_kernel,
                         cudaFuncAttributeMaxDynamicSharedMemorySize, MM_SMEM);

    // Weight splits (independent; run first)
    wsplit_kernel<<<(256 * 128 + 255) / 256, 256>>>(W4, 256 * 128, 0);
    wsplit_kernel<<<(1024 * 512 + 255) / 256, 256>>>(W5, 1024 * 512, 1);

    // 1) KNN
    knn_kernel<<<B_SZ * 8, 256>>>(x);

    // 2) conv1 -> y (M,64); nmax -> cat[:, 0:64]
    conv1_kernel<<<(M_TOT * 64) / 256, 256>>>(x, W1, g1, b1);
    nmax_kernel<64><<<M_TOT / 8, 128>>>(0);

    // 3) conv2 (fp32) -> nmax -> cat[:, 64:128]
    gemm_bn_lrelu_kernel<<<dim3(M_TOT / 64, 1), 256>>>(0, W2, g2, b2, 64, 64);
    nmax_kernel<64><<<M_TOT / 8, 128>>>(64);

    // 4) conv3 (fp32) -> nmax -> cat[:, 128:256]
    gemm_bn_lrelu_kernel<<<dim3(M_TOT / 64, 2), 256>>>(64, W3, g3, b3, 128, 64);
    nmax_kernel<128><<<M_TOT / 4, 128>>>(128);

    // 5) conv4 (mma bf16x3): A = cat[:,128:256], K=128, N=256
    mma_gemm_kernel<<<dim3(M_TOT / 128, 2), 256, MM_SMEM>>>(128, 0, g4, b4, 256, 128);
    nmax_kernel<256><<<M_TOT / 2, 128>>>(256);

    // 6) conv5 (mma bf16x3): A = cat[:,0:512], K=512, N=1024
    mma_gemm_kernel<<<dim3(M_TOT / 128, 8), 256, MM_SMEM>>>(0, 1, g5, b5, 1024, 512);

    // 7) max+mean pool
    reduce_kernel<<<dim3(B_SZ, 8), 128>>>();

    // 8) FC head
    head_kernel<<<B_SZ, 512>>>(L1W, g6, b6, L2W, L2b, g7, b7, L3W, L3b, out);
}